// round 14
// baseline (speedup 1.0000x reference)
#include <cuda_runtime.h>
#include <cuda_fp16.h>
#include <math.h>
#include <stdint.h>

#define NB 32768
#define DIN 784
#define DH 1024
#define DLAT 64
#define NK 8192
#define KP1 2368   // GEMM1: 3*784=2352 padded (duplicated-hi layout, proven)
#define KA2 2048   // GEMM2 A: [h1_hi(1024) | h1_lo(1024)]
#define KB2 3072   // GEMM2 W: [w_hi | w_hi | w_lo]
#define KP4 1024
#define NPAD4 896
#define WSCALE 64.0f
#define INV_WSCALE (1.0f / 64.0f)

typedef unsigned long long u64;
typedef unsigned int u32;

__device__ __half g_h1s[(size_t)NB * KA2];    // h1 split pair (128 MB)
__device__ __half g_h2[(size_t)NB * DH];
__device__ __half g_H3[(size_t)NK * DH];
__device__ __half g_a3h[(size_t)NB * KP1];
__device__ __half g_w1th[(size_t)DH * KP1];
__device__ __half g_w2s[(size_t)128 * KB2];   // W2 split, rows >=64 zero
__device__ __half g_w4t[(size_t)NPAD4 * KP4];
__device__ __half g_emb_h[(size_t)NK * DLAT];
__device__ __half g_ze_h[(size_t)NB * DLAT];
__device__ float  g_enorm[NK];
__device__ int    g_idx[NB];
__device__ int    g_cand[(size_t)NB * 64];

__device__ __forceinline__ u64 pack2(float lo, float hi) {
    u64 r; asm("mov.b64 %0, {%1,%2};" : "=l"(r) : "f"(lo), "f"(hi)); return r;
}
__device__ __forceinline__ void unpack2(u64 v, float& lo, float& hi) {
    asm("mov.b64 {%0,%1}, %2;" : "=f"(lo), "=f"(hi) : "l"(v));
}
__device__ __forceinline__ void fma2(u64& acc, u64 a, u64 b) {
    asm("fma.rn.f32x2 %0, %1, %2, %0;" : "+l"(acc) : "l"(a), "l"(b));
}
__device__ __forceinline__ u32 smem_u32(const void* p) {
    u32 a;
    asm("{ .reg .u64 t; cvta.to.shared.u64 t, %1; cvt.u32.u64 %0, t; }" : "=r"(a) : "l"(p));
    return a;
}
__device__ __forceinline__ void cp16(u32 dst, const void* src) {
    asm volatile("cp.async.cg.shared.global [%0], [%1], 16;" :: "r"(dst), "l"(src));
}
#define CP_COMMIT() asm volatile("cp.async.commit_group;" ::: "memory")
#define CP_WAIT1()  asm volatile("cp.async.wait_group 1;" ::: "memory")
#define CP_WAIT0()  asm volatile("cp.async.wait_group 0;" ::: "memory")

#define MMA_F16(acc, a, b) \
    asm volatile( \
        "mma.sync.aligned.m16n8k16.row.col.f32.f16.f16.f32 " \
        "{%0,%1,%2,%3}, {%4,%5,%6,%7}, {%8,%9}, {%0,%1,%2,%3};" \
        : "+f"((acc)[0]), "+f"((acc)[1]), "+f"((acc)[2]), "+f"((acc)[3]) \
        : "r"((a)[0]), "r"((a)[1]), "r"((a)[2]), "r"((a)[3]), \
          "r"((b)[0]), "r"((b)[1]))

#define MMA_F16_Z(acc, a, b) \
    asm volatile( \
        "mma.sync.aligned.m16n8k16.row.col.f32.f16.f16.f32 " \
        "{%0,%1,%2,%3}, {%4,%5,%6,%7}, {%8,%9}, {%10,%10,%10,%10};" \
        : "=f"((acc)[0]), "=f"((acc)[1]), "=f"((acc)[2]), "=f"((acc)[3]) \
        : "r"((a)[0]), "r"((a)[1]), "r"((a)[2]), "r"((a)[3]), \
          "r"((b)[0]), "r"((b)[1]), "f"(0.f))

// ---- prep kernels -----------------------------------------------------------
__global__ void split3_A_h(const float* __restrict__ in, __half* __restrict__ out,
                           int K, int KP)
{
    size_t t = blockIdx.x * (size_t)blockDim.x + threadIdx.x;
    if (t >= (size_t)NB * (K / 4)) return;
    int m = (int)(t / (K / 4));
    int kq = (int)(t % (K / 4)) * 4;
    float4 v = *reinterpret_cast<const float4*>(&in[(size_t)m * K + kq]);
    __half hx = __float2half_rn(v.x), hy = __float2half_rn(v.y);
    __half hz = __float2half_rn(v.z), hw = __float2half_rn(v.w);
    __half2 hi0 = __halves2half2(hx, hy), hi1 = __halves2half2(hz, hw);
    __half2 lo0 = __floats2half2_rn(v.x - __half2float(hx), v.y - __half2float(hy));
    __half2 lo1 = __floats2half2_rn(v.z - __half2float(hz), v.w - __half2float(hw));
    __half* o = &out[(size_t)m * KP1];
    *reinterpret_cast<__half2*>(&o[kq])             = hi0;
    *reinterpret_cast<__half2*>(&o[kq + 2])         = hi1;
    *reinterpret_cast<__half2*>(&o[K + kq])         = lo0;
    *reinterpret_cast<__half2*>(&o[K + kq + 2])     = lo1;
    *reinterpret_cast<__half2*>(&o[2 * K + kq])     = hi0;
    *reinterpret_cast<__half2*>(&o[2 * K + kq + 2]) = hi1;
}

__global__ void zero_tail_A_h(__half* __restrict__ out, int K3, int KP)
{
    int w = KP - K3;
    size_t t = blockIdx.x * (size_t)blockDim.x + threadIdx.x;
    if (t >= (size_t)NB * w) return;
    out[(size_t)(t / w) * KP + K3 + (int)(t % w)] = __float2half_rn(0.f);
}

// W split (scaled): out[n, kp] = [ w_hi | w_hi | w_lo ], rows >= N zero
__global__ void split3_WT_h(const float* __restrict__ W, __half* __restrict__ out,
                            int K, int N, int NA, int KP)
{
    size_t t = blockIdx.x * (size_t)blockDim.x + threadIdx.x;
    if (t >= (size_t)NA * KP) return;
    int n = (int)(t / KP);
    int kp = (int)(t % KP);
    float val = 0.0f;
    if (n < N) {
        if (kp < K) {
            val = __half2float(__float2half_rn(W[(size_t)kp * N + n] * WSCALE));
        } else if (kp < 2 * K) {
            val = __half2float(__float2half_rn(W[(size_t)(kp - K) * N + n] * WSCALE));
        } else if (kp < 3 * K) {
            float a = W[(size_t)(kp - 2 * K) * N + n] * WSCALE;
            val = a - __half2float(__float2half_rn(a));
        }
    }
    out[t] = __float2half_rn(val);
}

__global__ void round_WT_h(const float* __restrict__ W, __half* __restrict__ out,
                           int K, int N, int NA)
{
    size_t t = blockIdx.x * (size_t)blockDim.x + threadIdx.x;
    if (t >= (size_t)NA * K) return;
    int n = (int)(t / K);
    int k = (int)(t % K);
    out[t] = (n < N) ? __float2half_rn(W[(size_t)k * N + n]) : __float2half_rn(0.f);
}

__global__ void f2h_kernel(const float4* __restrict__ in, __half2* __restrict__ out, int n4)
{
    int t = blockIdx.x * blockDim.x + threadIdx.x;
    if (t >= n4) return;
    float4 v = in[t];
    out[2 * t + 0] = __floats2half2_rn(v.x, v.y);
    out[2 * t + 1] = __floats2half2_rn(v.z, v.w);
}

// row-copy gather: h2[m] = H3[idx[m]]
__global__ void gather_h2_kernel(const int* __restrict__ idx,
                                 const __half* __restrict__ H3, __half* __restrict__ h2)
{
    size_t t = blockIdx.x * (size_t)blockDim.x + threadIdx.x;   // NB*128
    int m = (int)(t >> 7), q = (int)(t & 127);
    const int4* src = reinterpret_cast<const int4*>(H3 + (size_t)idx[m] * DH);
    reinterpret_cast<int4*>(h2 + (size_t)m * DH)[q] = src[q];
}

// ---------------------------------------------------------------------------
// FP16 tensor-core GEMM: C = act(scale * (A[.,KA] @ WT[:,KB]^T) + bias)
// SPLITA: A-block remap threshold in 64-blocks (0 = KA==KB direct).
// ACT: 0 = none (float out), 1 = relu (float out), 2 = sigmoid (float out),
//      3 = relu + split write to half buffer [hi(1024) | lo(1024)] stride KA2.
// ---------------------------------------------------------------------------
#define MMA_SMEM (2 * 128 * 72 * 2 * 2)   // 73728 bytes

template<int ACT, int SPLITA>
__global__ void __launch_bounds__(256)
hmma_gemm(const __half* __restrict__ A, const __half* __restrict__ WT,
          const float* __restrict__ bias, void* __restrict__ Cv,
          int KA, int KB, int Nout, float scale)
{
    extern __shared__ __half smh[];
    __half* As = smh;                   // [2][128][72]
    __half* Bs = smh + 2 * 128 * 72;
    const u32 As_b = smem_u32(As), Bs_b = smem_u32(Bs);

    const int tid = threadIdx.x, lane = tid & 31, wid = tid >> 5;
    const int wm = (wid & 1) * 64, wn = (wid >> 1) * 32;
    const int m0 = blockIdx.y * 128, n0 = blockIdx.x * 128;

    float acc[4][4][4];
    #pragma unroll
    for (int i = 0; i < 4; i++)
        #pragma unroll
        for (int j = 0; j < 4; j++)
            #pragma unroll
            for (int k = 0; k < 4; k++) acc[i][j][k] = 0.f;

    const int nkb = KB / 64;
    const __half* Ag = A + (size_t)m0 * KA;
    const __half* Bg = WT + (size_t)n0 * KB;
    const int srow = tid >> 3, skq = tid & 7;

    #define HSTAGE(buf, kbB, kbA) do { \
        _Pragma("unroll") \
        for (int i = 0; i < 4; i++) { \
            int row = srow + i * 32; \
            cp16(As_b + ((buf) * 9216 + row * 72 + skq * 8) * 2, \
                 Ag + (size_t)row * KA + (kbA) * 64 + skq * 8); \
        } \
        _Pragma("unroll") \
        for (int i = 0; i < 4; i++) { \
            int row = srow + i * 32; \
            cp16(Bs_b + ((buf) * 9216 + row * 72 + skq * 8) * 2, \
                 Bg + (size_t)row * KB + (kbB) * 64 + skq * 8); \
        } \
        CP_COMMIT(); \
    } while (0)

    HSTAGE(0, 0, 0);
    HSTAGE(1, 1, 1);

    const int r = lane >> 2, cc = lane & 3;

    for (int kb = 0; kb < nkb; kb++) {
        const int buf = kb & 1;
        if (kb + 1 < nkb) CP_WAIT1(); else CP_WAIT0();
        __syncthreads();

        const __half* Asb = As + buf * 9216;
        const __half* Bsb = Bs + buf * 9216;
        #pragma unroll
        for (int ks = 0; ks < 4; ks++) {
            u32 a[4][4], b[4][2];
            #pragma unroll
            for (int mt = 0; mt < 4; mt++) {
                const __half* p = Asb + (wm + mt * 16 + r) * 72 + ks * 16 + 2 * cc;
                a[mt][0] = *reinterpret_cast<const u32*>(p);
                a[mt][1] = *reinterpret_cast<const u32*>(p + 8 * 72);
                a[mt][2] = *reinterpret_cast<const u32*>(p + 8);
                a[mt][3] = *reinterpret_cast<const u32*>(p + 8 * 72 + 8);
            }
            #pragma unroll
            for (int nt = 0; nt < 4; nt++) {
                const __half* q = Bsb + (wn + nt * 8 + r) * 72 + ks * 16 + 2 * cc;
                b[nt][0] = *reinterpret_cast<const u32*>(q);
                b[nt][1] = *reinterpret_cast<const u32*>(q + 8);
            }
            #pragma unroll
            for (int mt = 0; mt < 4; mt++)
                #pragma unroll
                for (int nt = 0; nt < 4; nt++)
                    MMA_F16(acc[mt][nt], a[mt], b[nt]);
        }
        __syncthreads();
        if (kb + 2 < nkb) {
            int kn = kb + 2;
            int akn = (SPLITA && kn >= SPLITA) ? kn - SPLITA : kn;
            HSTAGE(buf, kn, akn);
        }
    }
    #undef HSTAGE

    #pragma unroll
    for (int mt = 0; mt < 4; mt++) {
        int row0 = m0 + wm + mt * 16 + r;
        #pragma unroll
        for (int nt = 0; nt < 4; nt++) {
            int col = n0 + wn + nt * 8 + 2 * cc;
            if (col < Nout) {
                float bx = bias[col], by = bias[col + 1];
                float v0 = fmaf(acc[mt][nt][0], scale, bx);
                float v1 = fmaf(acc[mt][nt][1], scale, by);
                float v2 = fmaf(acc[mt][nt][2], scale, bx);
                float v3 = fmaf(acc[mt][nt][3], scale, by);
                if (ACT == 1 || ACT == 3) {
                    v0 = fmaxf(v0, 0.f); v1 = fmaxf(v1, 0.f);
                    v2 = fmaxf(v2, 0.f); v3 = fmaxf(v3, 0.f);
                } else if (ACT == 2) {
                    v0 = 1.f / (1.f + expf(-v0)); v1 = 1.f / (1.f + expf(-v1));
                    v2 = 1.f / (1.f + expf(-v2)); v3 = 1.f / (1.f + expf(-v3));
                }
                if (ACT == 3) {
                    __half* Ch = (__half*)Cv;
                    __half h0 = __float2half_rn(v0), h1x = __float2half_rn(v1);
                    __half h2x = __float2half_rn(v2), h3 = __float2half_rn(v3);
                    size_t b0 = (size_t)row0 * KA2 + col;
                    size_t b1 = (size_t)(row0 + 8) * KA2 + col;
                    *reinterpret_cast<__half2*>(&Ch[b0]) = __halves2half2(h0, h1x);
                    *reinterpret_cast<__half2*>(&Ch[b0 + 1024]) =
                        __floats2half2_rn(v0 - __half2float(h0), v1 - __half2float(h1x));
                    *reinterpret_cast<__half2*>(&Ch[b1]) = __halves2half2(h2x, h3);
                    *reinterpret_cast<__half2*>(&Ch[b1 + 1024]) =
                        __floats2half2_rn(v2 - __half2float(h2x), v3 - __half2float(h3));
                } else {
                    float* C = (float*)Cv;
                    *reinterpret_cast<float2*>(&C[(size_t)row0 * Nout + col]) = make_float2(v0, v1);
                    *reinterpret_cast<float2*>(&C[(size_t)(row0 + 8) * Nout + col]) = make_float2(v2, v3);
                }
            }
        }
    }
}

// ---------------------------------------------------------------------------
// Phase 1 (fp16): approx distances, top-4 candidates (proven)
// ---------------------------------------------------------------------------
#define CAND_SMEM_H (3 * 128 * 72 * 2)   // 55296 bytes

__global__ void __launch_bounds__(256)
cand_kernel_h(const __half* __restrict__ zeh, const __half* __restrict__ embh,
              const float* __restrict__ enorm, int* __restrict__ cand)
{
    extern __shared__ __half smh[];
    __half* Zs = smh;
    __half* Es = smh + 128 * 72;
    const u32 Zb = smem_u32(Zs), Eb = smem_u32(Es);

    const int tid = threadIdx.x, lane = tid & 31, wid = tid >> 5;
    const int r = lane >> 2, cc = lane & 3;
    const int wm = (wid & 1) * 64, wn = (wid >> 1) * 32;
    const int m0 = blockIdx.x * 128;

    #pragma unroll
    for (int i = 0; i < 4; i++) {
        int idx = tid + i * 256;
        int row = idx >> 3, chk = idx & 7;
        cp16(Zb + (row * 72 + chk * 8) * 2, zeh + (size_t)(m0 + row) * 64 + chk * 8);
    }
    CP_COMMIT();

    #define ESTAGE(buf, chunk) do { \
        _Pragma("unroll") \
        for (int i = 0; i < 4; i++) { \
            int idx = tid + i * 256; \
            int row = idx >> 3, chk = idx & 7; \
            cp16(Eb + ((buf) * 9216 + row * 72 + chk * 8) * 2, \
                 embh + (size_t)((chunk) * 128 + row) * 64 + chk * 8); \
        } \
        CP_COMMIT(); \
    } while (0)

    ESTAGE(0, 0);
    ESTAGE(1, 1);

    float bv[8][4]; int bi[8][4];
    #pragma unroll
    for (int i = 0; i < 8; i++)
        #pragma unroll
        for (int j = 0; j < 4; j++) { bv[i][j] = 3.4e38f; bi[i][j] = 0; }

    for (int ch = 0; ch < 64; ch++) {
        const int buf = ch & 1;
        if (ch + 1 < 64) CP_WAIT1(); else CP_WAIT0();
        __syncthreads();

        float acc[4][4][4];
        const __half* Ef = Es + buf * 9216;
        #pragma unroll
        for (int ks = 0; ks < 4; ks++) {
            u32 a[4][4], b[4][2];
            #pragma unroll
            for (int mt = 0; mt < 4; mt++) {
                const __half* p = Zs + (wm + mt * 16 + r) * 72 + ks * 16 + 2 * cc;
                a[mt][0] = *reinterpret_cast<const u32*>(p);
                a[mt][1] = *reinterpret_cast<const u32*>(p + 8 * 72);
                a[mt][2] = *reinterpret_cast<const u32*>(p + 8);
                a[mt][3] = *reinterpret_cast<const u32*>(p + 8 * 72 + 8);
            }
            #pragma unroll
            for (int nt = 0; nt < 4; nt++) {
                const __half* q = Ef + (wn + nt * 8 + r) * 72 + ks * 16 + 2 * cc;
                b[nt][0] = *reinterpret_cast<const u32*>(q);
                b[nt][1] = *reinterpret_cast<const u32*>(q + 8);
            }
            if (ks == 0) {
                #pragma unroll
                for (int mt = 0; mt < 4; mt++)
                    #pragma unroll
                    for (int nt = 0; nt < 4; nt++)
                        MMA_F16_Z(acc[mt][nt], a[mt], b[nt]);
            } else {
                #pragma unroll
                for (int mt = 0; mt < 4; mt++)
                    #pragma unroll
                    for (int nt = 0; nt < 4; nt++)
                        MMA_F16(acc[mt][nt], a[mt], b[nt]);
            }
        }

        const int c0 = ch * 128;
        #pragma unroll
        for (int nt = 0; nt < 4; nt++) {
            int cbase = c0 + wn + nt * 8 + 2 * cc;
            float2 en = *reinterpret_cast<const float2*>(&enorm[cbase]);
            #pragma unroll
            for (int mt = 0; mt < 4; mt++) {
                #pragma unroll
                for (int j = 0; j < 4; j++) {
                    float d = fmaf(-2.f, acc[mt][nt][j], (j & 1) ? en.y : en.x);
                    int code = cbase + (j & 1);
                    int rr = mt * 2 + (j >> 1);
                    if (d < bv[rr][3]) {
                        if (d < bv[rr][1]) {
                            bv[rr][3] = bv[rr][2]; bi[rr][3] = bi[rr][2];
                            bv[rr][2] = bv[rr][1]; bi[rr][2] = bi[rr][1];
                            if (d < bv[rr][0]) {
                                bv[rr][1] = bv[rr][0]; bi[rr][1] = bi[rr][0];
                                bv[rr][0] = d; bi[rr][0] = code;
                            } else { bv[rr][1] = d; bi[rr][1] = code; }
                        } else {
                            if (d < bv[rr][2]) {
                                bv[rr][3] = bv[rr][2]; bi[rr][3] = bi[rr][2];
                                bv[rr][2] = d; bi[rr][2] = code;
                            } else { bv[rr][3] = d; bi[rr][3] = code; }
                        }
                    }
                }
            }
        }
        __syncthreads();
        if (ch + 2 < 64) ESTAGE(buf, ch + 2);
    }
    #undef ESTAGE

    const int sbase = ((wid >> 1) * 4 + cc) * 4;
    #pragma unroll
    for (int rr = 0; rr < 8; rr++) {
        int row = m0 + wm + (rr >> 1) * 16 + r + (rr & 1) * 8;
        *reinterpret_cast<int4*>(&cand[(size_t)row * 64 + sbase]) =
            make_int4(bi[rr][0], bi[rr][1], bi[rr][2], bi[rr][3]);
    }
}

// ---------------------------------------------------------------------------
// Phase 2: exact fp32 rescore + fused z_q write
// ---------------------------------------------------------------------------
__global__ void __launch_bounds__(256)
rescore_kernel(const float* __restrict__ ze, const float* __restrict__ emb,
               const float* __restrict__ enorm, const int* __restrict__ cand,
               int* __restrict__ out_idx, float* __restrict__ zq)
{
    __shared__ float sred[4][2];
    __shared__ int   sidx[4][2];
    __shared__ int   swin[4];
    const int tid = threadIdx.x;
    const int rowloc = tid >> 6, l = tid & 63, lane = tid & 31;
    const int row = blockIdx.x * 4 + rowloc;

    int c = cand[(size_t)row * 64 + l];
    const float4* zp = reinterpret_cast<const float4*>(ze + (size_t)row * 64);
    const float4* ep = reinterpret_cast<const float4*>(emb + (size_t)c * 64);
    float s = 0.f;
    #pragma unroll
    for (int q = 0; q < 16; q++) {
        float4 z4 = zp[q], e4 = ep[q];
        s = fmaf(z4.x, e4.x, s); s = fmaf(z4.y, e4.y, s);
        s = fmaf(z4.z, e4.z, s); s = fmaf(z4.w, e4.w, s);
    }
    float d = fmaf(-2.f, s, enorm[c]);

    #pragma unroll
    for (int off = 16; off; off >>= 1) {
        float od = __shfl_xor_sync(0xffffffffu, d, off);
        int   oc = __shfl_xor_sync(0xffffffffu, c, off);
        if (od < d || (od == d && oc < c)) { d = od; c = oc; }
    }
    const int wl = (tid >> 5) & 1;
    if (lane == 0) { sred[rowloc][wl] = d; sidx[rowloc][wl] = c; }
    __syncthreads();
    if (l == 0) {
        float d0 = sred[rowloc][0], d1 = sred[rowloc][1];
        int   i0 = sidx[rowloc][0], i1 = sidx[rowloc][1];
        int win = (d1 < d0 || (d1 == d0 && i1 < i0)) ? i1 : i0;
        out_idx[row] = win;
        swin[rowloc] = win;
    }
    __syncthreads();
    int wc = swin[rowloc];
    zq[(size_t)row * 64 + l] = emb[(size_t)wc * 64 + l];
}

// ---- FFMA SGEMM (H3 precompute only); ACT 4 = relu + fp16 out ---------------
template<int BM, int BN, int BK, int ACT>
__global__ void __launch_bounds__((BM/8)*(BN/8))
sgemm_bias_act(const float* __restrict__ A, const float* __restrict__ W,
               const float* __restrict__ bias, float* __restrict__ C,
               int M, int N, int Kd)
{
    constexpr int TM = 8, TN = 8;
    constexpr int THREADS = (BM/TM) * (BN/TN);
    __shared__ __align__(16) float Ash[BK][BM];
    __shared__ __align__(16) float Wsh[BK][BN];

    const int tid = threadIdx.x;
    const int tx = tid % (BN/TN), ty = tid / (BN/TN);
    const int m0 = blockIdx.y * BM, n0 = blockIdx.x * BN;

    u64 acc[TM][TN/2];
    #pragma unroll
    for (int i = 0; i < TM; i++)
        #pragma unroll
        for (int j = 0; j < TN/2; j++) acc[i][j] = 0ull;

    for (int k0 = 0; k0 < Kd; k0 += BK) {
        constexpr int AV = (BM * BK) / (THREADS * 4);
        #pragma unroll
        for (int it = 0; it < AV; ++it) {
            int li = tid + it * THREADS;
            int m = li / (BK/4), kq = li % (BK/4);
            float4 v = *reinterpret_cast<const float4*>(&A[(size_t)(m0 + m) * Kd + k0 + kq*4]);
            Ash[kq*4+0][m] = v.x; Ash[kq*4+1][m] = v.y;
            Ash[kq*4+2][m] = v.z; Ash[kq*4+3][m] = v.w;
        }
        constexpr int WV = (BK * BN) / (THREADS * 4);
        #pragma unroll
        for (int it = 0; it < WV; ++it) {
            int li = tid + it * THREADS;
            int k = li / (BN/4), nq = li % (BN/4);
            int n = n0 + nq*4;
            float4 v = make_float4(0.f, 0.f, 0.f, 0.f);
            if (n < N) v = *reinterpret_cast<const float4*>(&W[(size_t)(k0 + k) * N + n]);
            *reinterpret_cast<float4*>(&Wsh[k][nq*4]) = v;
        }
        __syncthreads();
        #pragma unroll
        for (int k = 0; k < BK; k++) {
            float4 a0 = *reinterpret_cast<const float4*>(&Ash[k][ty*TM]);
            float4 a1 = *reinterpret_cast<const float4*>(&Ash[k][ty*TM + 4]);
            float a[TM] = {a0.x, a0.y, a0.z, a0.w, a1.x, a1.y, a1.z, a1.w};
            const u64* wr = reinterpret_cast<const u64*>(&Wsh[k][tx*TN]);
            u64 b2[TN/2];
            #pragma unroll
            for (int j = 0; j < TN/2; j++) b2[j] = wr[j];
            #pragma unroll
            for (int i = 0; i < TM; i++) {
                u64 ad = pack2(a[i], a[i]);
                #pragma unroll
                for (int j = 0; j < TN/2; j++) fma2(acc[i][j], ad, b2[j]);
            }
        }
        __syncthreads();
    }
    #pragma unroll
    for (int i = 0; i < TM; i++) {
        int m = m0 + ty*TM + i;
        #pragma unroll
        for (int j = 0; j < TN/2; j++) {
            int n = n0 + tx*TN + j*2;
            if (n < N) {
                float lo, hi; unpack2(acc[i][j], lo, hi);
                lo += bias[n]; hi += bias[n+1];
                if (ACT == 4) {
                    lo = fmaxf(lo, 0.f); hi = fmaxf(hi, 0.f);
                    __half* Ch = reinterpret_cast<__half*>(C);
                    *reinterpret_cast<__half2*>(&Ch[(size_t)m * N + n]) =
                        __floats2half2_rn(lo, hi);
                } else {
                    *reinterpret_cast<float2*>(&C[(size_t)m * N + n]) = make_float2(lo, hi);
                }
            }
        }
    }
}

// ---- emb norms --------------------------------------------------------------
__global__ void emb_norms_kernel(const float* __restrict__ emb, float* __restrict__ enorm)
{
    int g = (blockIdx.x * blockDim.x + threadIdx.x) >> 5;
    int lane = threadIdx.x & 31;
    if (g >= NK) return;
    float a = emb[(size_t)g * 64 + lane];
    float b = emb[(size_t)g * 64 + 32 + lane];
    float s = a*a + b*b;
    #pragma unroll
    for (int off = 16; off; off >>= 1) s += __shfl_xor_sync(0xffffffffu, s, off);
    if (lane == 0) enorm[g] = s;
}

// ---------------------------------------------------------------------------
extern "C" void kernel_launch(void* const* d_in, const int* in_sizes, int n_in,
                              void* d_out, int out_size)
{
    const float* x   = (const float*)d_in[0];
    const float* W1  = (const float*)d_in[1];
    const float* b1  = (const float*)d_in[2];
    const float* W2  = (const float*)d_in[3];
    const float* b2  = (const float*)d_in[4];
    const float* W3  = (const float*)d_in[5];
    const float* b3  = (const float*)d_in[6];
    const float* W4  = (const float*)d_in[7];
    const float* b4  = (const float*)d_in[8];
    const float* emb = (const float*)d_in[9];

    float* out     = (float*)d_out;
    float* x_recon = out;
    float* z_e     = out + (size_t)NB * DIN;
    float* z_q     = z_e + (size_t)NB * DLAT;

    float *enorm; __half *h1s, *h2, *H3, *a3h, *w1th, *w2s, *w4t, *embh, *zeh;
    int *idxp, *candp;
    cudaGetSymbolAddress((void**)&h1s, g_h1s);
    cudaGetSymbolAddress((void**)&h2, g_h2);
    cudaGetSymbolAddress((void**)&H3, g_H3);
    cudaGetSymbolAddress((void**)&a3h, g_a3h);
    cudaGetSymbolAddress((void**)&w1th, g_w1th);
    cudaGetSymbolAddress((void**)&w2s, g_w2s);
    cudaGetSymbolAddress((void**)&w4t, g_w4t);
    cudaGetSymbolAddress((void**)&embh, g_emb_h);
    cudaGetSymbolAddress((void**)&zeh, g_ze_h);
    cudaGetSymbolAddress((void**)&enorm, g_enorm);
    cudaGetSymbolAddress((void**)&idxp, g_idx);
    cudaGetSymbolAddress((void**)&candp, g_cand);

    cudaFuncSetAttribute((const void*)hmma_gemm<3,0>, cudaFuncAttributeMaxDynamicSharedMemorySize, MMA_SMEM);
    cudaFuncSetAttribute((const void*)hmma_gemm<0,32>, cudaFuncAttributeMaxDynamicSharedMemorySize, MMA_SMEM);
    cudaFuncSetAttribute((const void*)hmma_gemm<2,0>, cudaFuncAttributeMaxDynamicSharedMemorySize, MMA_SMEM);
    cudaFuncSetAttribute((const void*)cand_kernel_h, cudaFuncAttributeMaxDynamicSharedMemorySize, CAND_SMEM_H);

    emb_norms_kernel<<<NK/8, 256>>>(emb, enorm);
    f2h_kernel<<<(NK*DLAT/4 + 255)/256, 256>>>((const float4*)emb, (__half2*)embh, NK*DLAT/4);
    {   size_t tot = (size_t)DH * KP1;
        split3_WT_h<<<(unsigned)((tot + 255)/256), 256>>>(W1, w1th, DIN, DH, DH, KP1); }
    {   size_t tot = (size_t)128 * KB2;
        split3_WT_h<<<(unsigned)((tot + 255)/256), 256>>>(W2, w2s, DH, DLAT, 128, KB2); }
    {   size_t tot = (size_t)NPAD4 * KP4;
        round_WT_h<<<(unsigned)((tot + 255)/256), 256>>>(W4, w4t, DH, DIN, NPAD4); }

    // H3[c] = half(relu(emb[c] @ W3 + b3)) over 8192 codes
    sgemm_bias_act<128,128,16,4><<<dim3(DH/128, NK/128), 256>>>(
        emb, W3, b3, (float*)H3, NK, DH, DLAT);

    {   size_t tot = (size_t)NB * (DIN/4);
        split3_A_h<<<(unsigned)((tot + 255)/256), 256>>>(x, a3h, DIN, KP1);
        size_t tt = (size_t)NB * (KP1 - 3*DIN);
        zero_tail_A_h<<<(unsigned)((tt + 255)/256), 256>>>(a3h, 3*DIN, KP1); }

    // h1 = relu((x @ 64*W1)/64 + b1), written pre-split [hi|lo] fp16 (ACT=3)
    hmma_gemm<3,0><<<dim3(DH/128, NB/128), 256, MMA_SMEM>>>(
        a3h, w1th, b1, h1s, KP1, KP1, DH, INV_WSCALE);

    // z_e = (h1 @ 64*W2)/64 + b2   [3xFP16 split on tensor cores, fp32-class]
    hmma_gemm<0,32><<<dim3(1, NB/128), 256, MMA_SMEM>>>(
        h1s, w2s, b2, z_e, KA2, KB2, DLAT, INV_WSCALE);

    // z_e -> fp16 for approx phase
    f2h_kernel<<<(NB*DLAT/4 + 255)/256, 256>>>((const float4*)z_e, (__half2*)zeh, NB*DLAT/4);

    // argmin: fp16 approx tensor phase + exact fp32 rescore (+ fused z_q write)
    cand_kernel_h<<<NB/128, 256, CAND_SMEM_H>>>(zeh, embh, enorm, candp);
    rescore_kernel<<<NB/4, 256>>>(z_e, emb, enorm, candp, idxp, z_q);

    // h2[m] = H3[idx[m]]  (row-copy gather)
    gather_h2_kernel<<<(unsigned)(((size_t)NB*128 + 255)/256), 256>>>(idxp, H3, h2);

    // x_recon = sigmoid(h2 @ W4 + b4)
    hmma_gemm<2,0><<<dim3(NPAD4/128, NB/128), 256, MMA_SMEM>>>(
        h2, w4t, b4, x_recon, KP4, KP4, DIN, 1.0f);
}

// round 15
// speedup vs baseline: 1.0903x; 1.0903x over previous
#include <cuda_runtime.h>
#include <cuda_fp16.h>
#include <math.h>
#include <stdint.h>

#define NB 32768
#define DIN 784
#define DH 1024
#define DLAT 64
#define NK 8192
#define KP1 2368   // 3*784=2352 padded to 64-multiple
#define KP4 1024
#define NPAD4 896
#define WSCALE 64.0f
#define INV_WSCALE (1.0f / 64.0f)

typedef unsigned long long u64;
typedef unsigned int u32;

__device__ float  g_h1[(size_t)NB * DH];
__device__ __half g_h2[(size_t)NB * DH];
__device__ __half g_H3[(size_t)NK * DH];      // per-code decoder hidden (16 MB)
__device__ __half g_a3h[(size_t)NB * KP1];
__device__ __half g_w1th[(size_t)DH * KP1];
__device__ __half g_w4t[(size_t)NPAD4 * KP4];
__device__ __half g_emb_h[(size_t)NK * DLAT];
__device__ __half g_ze_h[(size_t)NB * DLAT];
__device__ float  g_enorm[NK];
__device__ int    g_idx[NB];
__device__ int    g_cand[(size_t)NB * 64];

__device__ __forceinline__ u64 pack2(float lo, float hi) {
    u64 r; asm("mov.b64 %0, {%1,%2};" : "=l"(r) : "f"(lo), "f"(hi)); return r;
}
__device__ __forceinline__ void unpack2(u64 v, float& lo, float& hi) {
    asm("mov.b64 {%0,%1}, %2;" : "=f"(lo), "=f"(hi) : "l"(v));
}
__device__ __forceinline__ void fma2(u64& acc, u64 a, u64 b) {
    asm("fma.rn.f32x2 %0, %1, %2, %0;" : "+l"(acc) : "l"(a), "l"(b));
}
__device__ __forceinline__ u32 smem_u32(const void* p) {
    u32 a;
    asm("{ .reg .u64 t; cvta.to.shared.u64 t, %1; cvt.u32.u64 %0, t; }" : "=r"(a) : "l"(p));
    return a;
}
__device__ __forceinline__ void cp16(u32 dst, const void* src) {
    asm volatile("cp.async.cg.shared.global [%0], [%1], 16;" :: "r"(dst), "l"(src));
}
#define CP_COMMIT() asm volatile("cp.async.commit_group;" ::: "memory")
#define CP_WAIT1()  asm volatile("cp.async.wait_group 1;" ::: "memory")
#define CP_WAIT0()  asm volatile("cp.async.wait_group 0;" ::: "memory")

#define MMA_F16(acc, a, b) \
    asm volatile( \
        "mma.sync.aligned.m16n8k16.row.col.f32.f16.f16.f32 " \
        "{%0,%1,%2,%3}, {%4,%5,%6,%7}, {%8,%9}, {%0,%1,%2,%3};" \
        : "+f"((acc)[0]), "+f"((acc)[1]), "+f"((acc)[2]), "+f"((acc)[3]) \
        : "r"((a)[0]), "r"((a)[1]), "r"((a)[2]), "r"((a)[3]), \
          "r"((b)[0]), "r"((b)[1]))

#define MMA_F16_Z(acc, a, b) \
    asm volatile( \
        "mma.sync.aligned.m16n8k16.row.col.f32.f16.f16.f32 " \
        "{%0,%1,%2,%3}, {%4,%5,%6,%7}, {%8,%9}, {%10,%10,%10,%10};" \
        : "=f"((acc)[0]), "=f"((acc)[1]), "=f"((acc)[2]), "=f"((acc)[3]) \
        : "r"((a)[0]), "r"((a)[1]), "r"((a)[2]), "r"((a)[3]), \
          "r"((b)[0]), "r"((b)[1]), "f"(0.f))

// ---- prep kernels -----------------------------------------------------------
__global__ void split3_A_h(const float* __restrict__ in, __half* __restrict__ out,
                           int K, int KP)
{
    size_t t = blockIdx.x * (size_t)blockDim.x + threadIdx.x;
    if (t >= (size_t)NB * (K / 4)) return;
    int m = (int)(t / (K / 4));
    int kq = (int)(t % (K / 4)) * 4;
    float4 v = *reinterpret_cast<const float4*>(&in[(size_t)m * K + kq]);
    __half hx = __float2half_rn(v.x), hy = __float2half_rn(v.y);
    __half hz = __float2half_rn(v.z), hw = __float2half_rn(v.w);
    __half2 hi0 = __halves2half2(hx, hy), hi1 = __halves2half2(hz, hw);
    __half2 lo0 = __floats2half2_rn(v.x - __half2float(hx), v.y - __half2float(hy));
    __half2 lo1 = __floats2half2_rn(v.z - __half2float(hz), v.w - __half2float(hw));
    __half* o = &out[(size_t)m * KP1];
    *reinterpret_cast<__half2*>(&o[kq])             = hi0;
    *reinterpret_cast<__half2*>(&o[kq + 2])         = hi1;
    *reinterpret_cast<__half2*>(&o[K + kq])         = lo0;
    *reinterpret_cast<__half2*>(&o[K + kq + 2])     = lo1;
    *reinterpret_cast<__half2*>(&o[2 * K + kq])     = hi0;
    *reinterpret_cast<__half2*>(&o[2 * K + kq + 2]) = hi1;
}

__global__ void zero_tail_A_h(__half* __restrict__ out, int K3, int KP)
{
    int w = KP - K3;
    size_t t = blockIdx.x * (size_t)blockDim.x + threadIdx.x;
    if (t >= (size_t)NB * w) return;
    out[(size_t)(t / w) * KP + K3 + (int)(t % w)] = __float2half_rn(0.f);
}

// W split (scaled by WSCALE): out[n, kp] = [ w_hi | w_hi | w_lo ], tail zero
__global__ void split3_WT_h(const float* __restrict__ W, __half* __restrict__ out,
                            int K, int N, int NA, int KP)
{
    size_t t = blockIdx.x * (size_t)blockDim.x + threadIdx.x;
    if (t >= (size_t)NA * KP) return;
    int n = (int)(t / KP);
    int kp = (int)(t % KP);
    float val = 0.0f;
    if (n < N) {
        if (kp < K) {
            val = __half2float(__float2half_rn(W[(size_t)kp * N + n] * WSCALE));
        } else if (kp < 2 * K) {
            val = __half2float(__float2half_rn(W[(size_t)(kp - K) * N + n] * WSCALE));
        } else if (kp < 3 * K) {
            float a = W[(size_t)(kp - 2 * K) * N + n] * WSCALE;
            val = a - __half2float(__float2half_rn(a));
        }
    }
    out[t] = __float2half_rn(val);
}

__global__ void round_WT_h(const float* __restrict__ W, __half* __restrict__ out,
                           int K, int N, int NA)
{
    size_t t = blockIdx.x * (size_t)blockDim.x + threadIdx.x;
    if (t >= (size_t)NA * K) return;
    int n = (int)(t / K);
    int k = (int)(t % K);
    out[t] = (n < N) ? __float2half_rn(W[(size_t)k * N + n]) : __float2half_rn(0.f);
}

__global__ void f2h_kernel(const float4* __restrict__ in, __half2* __restrict__ out, int n4)
{
    int t = blockIdx.x * blockDim.x + threadIdx.x;
    if (t >= n4) return;
    float4 v = in[t];
    out[2 * t + 0] = __floats2half2_rn(v.x, v.y);
    out[2 * t + 1] = __floats2half2_rn(v.z, v.w);
}

// row-copy gather: h2[m] = H3[idx[m]]  (int4 = 8 halves/thread)
__global__ void gather_h2_kernel(const int* __restrict__ idx,
                                 const __half* __restrict__ H3, __half* __restrict__ h2)
{
    size_t t = blockIdx.x * (size_t)blockDim.x + threadIdx.x;   // NB*128
    int m = (int)(t >> 7), q = (int)(t & 127);
    const int4* src = reinterpret_cast<const int4*>(H3 + (size_t)idx[m] * DH);
    reinterpret_cast<int4*>(h2 + (size_t)m * DH)[q] = src[q];
}

// ---------------------------------------------------------------------------
// FP16 tensor-core GEMM: C[M,Nout] = act(scale * (A[M,K]h @ WT[:,K]h^T) + bias)
// 128x128 tile, BK=64, m16n8k16, cp.async double-buffered, stride 72 halves.
// ACT: 1 = relu (float out), 2 = sigmoid (float out)   [round-13 proven config]
// ---------------------------------------------------------------------------
#define MMA_SMEM (2 * 128 * 72 * 2 * 2)   // 73728 bytes

template<int ACT>
__global__ void __launch_bounds__(256)
hmma_gemm(const __half* __restrict__ A, const __half* __restrict__ WT,
          const float* __restrict__ bias, float* __restrict__ C,
          int K, int Nout, float scale)
{
    extern __shared__ __half smh[];
    __half* As = smh;                   // [2][128][72]
    __half* Bs = smh + 2 * 128 * 72;
    const u32 As_b = smem_u32(As), Bs_b = smem_u32(Bs);

    const int tid = threadIdx.x, lane = tid & 31, wid = tid >> 5;
    const int wm = (wid & 1) * 64, wn = (wid >> 1) * 32;
    const int m0 = blockIdx.y * 128, n0 = blockIdx.x * 128;

    float acc[4][4][4];
    #pragma unroll
    for (int i = 0; i < 4; i++)
        #pragma unroll
        for (int j = 0; j < 4; j++)
            #pragma unroll
            for (int k = 0; k < 4; k++) acc[i][j][k] = 0.f;

    const int nkb = K / 64;
    const __half* Ag = A + (size_t)m0 * K;
    const __half* Bg = WT + (size_t)n0 * K;
    const int srow = tid >> 3, skq = tid & 7;

    #define HSTAGE(buf, kb) do { \
        _Pragma("unroll") \
        for (int i = 0; i < 4; i++) { \
            int row = srow + i * 32; \
            cp16(As_b + ((buf) * 9216 + row * 72 + skq * 8) * 2, \
                 Ag + (size_t)row * K + (kb) * 64 + skq * 8); \
        } \
        _Pragma("unroll") \
        for (int i = 0; i < 4; i++) { \
            int row = srow + i * 32; \
            cp16(Bs_b + ((buf) * 9216 + row * 72 + skq * 8) * 2, \
                 Bg + (size_t)row * K + (kb) * 64 + skq * 8); \
        } \
        CP_COMMIT(); \
    } while (0)

    HSTAGE(0, 0);
    HSTAGE(1, 1);

    const int r = lane >> 2, cc = lane & 3;

    for (int kb = 0; kb < nkb; kb++) {
        const int buf = kb & 1;
        if (kb + 1 < nkb) CP_WAIT1(); else CP_WAIT0();
        __syncthreads();

        const __half* Asb = As + buf * 9216;
        const __half* Bsb = Bs + buf * 9216;
        #pragma unroll
        for (int ks = 0; ks < 4; ks++) {
            u32 a[4][4], b[4][2];
            #pragma unroll
            for (int mt = 0; mt < 4; mt++) {
                const __half* p = Asb + (wm + mt * 16 + r) * 72 + ks * 16 + 2 * cc;
                a[mt][0] = *reinterpret_cast<const u32*>(p);
                a[mt][1] = *reinterpret_cast<const u32*>(p + 8 * 72);
                a[mt][2] = *reinterpret_cast<const u32*>(p + 8);
                a[mt][3] = *reinterpret_cast<const u32*>(p + 8 * 72 + 8);
            }
            #pragma unroll
            for (int nt = 0; nt < 4; nt++) {
                const __half* q = Bsb + (wn + nt * 8 + r) * 72 + ks * 16 + 2 * cc;
                b[nt][0] = *reinterpret_cast<const u32*>(q);
                b[nt][1] = *reinterpret_cast<const u32*>(q + 8);
            }
            #pragma unroll
            for (int mt = 0; mt < 4; mt++)
                #pragma unroll
                for (int nt = 0; nt < 4; nt++)
                    MMA_F16(acc[mt][nt], a[mt], b[nt]);
        }
        __syncthreads();
        if (kb + 2 < nkb) HSTAGE(buf, kb + 2);
    }
    #undef HSTAGE

    #pragma unroll
    for (int mt = 0; mt < 4; mt++) {
        int row0 = m0 + wm + mt * 16 + r;
        #pragma unroll
        for (int nt = 0; nt < 4; nt++) {
            int col = n0 + wn + nt * 8 + 2 * cc;
            if (col < Nout) {
                float bx = bias[col], by = bias[col + 1];
                float v0 = fmaf(acc[mt][nt][0], scale, bx);
                float v1 = fmaf(acc[mt][nt][1], scale, by);
                float v2 = fmaf(acc[mt][nt][2], scale, bx);
                float v3 = fmaf(acc[mt][nt][3], scale, by);
                if (ACT == 1) {
                    v0 = fmaxf(v0, 0.f); v1 = fmaxf(v1, 0.f);
                    v2 = fmaxf(v2, 0.f); v3 = fmaxf(v3, 0.f);
                } else {
                    v0 = 1.f / (1.f + expf(-v0)); v1 = 1.f / (1.f + expf(-v1));
                    v2 = 1.f / (1.f + expf(-v2)); v3 = 1.f / (1.f + expf(-v3));
                }
                *reinterpret_cast<float2*>(&C[(size_t)row0 * Nout + col]) = make_float2(v0, v1);
                *reinterpret_cast<float2*>(&C[(size_t)(row0 + 8) * Nout + col]) = make_float2(v2, v3);
            }
        }
    }
}

// ---------------------------------------------------------------------------
// Phase 1 (fp16): approx distances, top-4 candidates per (thread,row) (proven)
// ---------------------------------------------------------------------------
#define CAND_SMEM_H (3 * 128 * 72 * 2)   // 55296 bytes

__global__ void __launch_bounds__(256)
cand_kernel_h(const __half* __restrict__ zeh, const __half* __restrict__ embh,
              const float* __restrict__ enorm, int* __restrict__ cand)
{
    extern __shared__ __half smh[];
    __half* Zs = smh;                    // [128][72]
    __half* Es = smh + 128 * 72;         // [2][128][72]
    const u32 Zb = smem_u32(Zs), Eb = smem_u32(Es);

    const int tid = threadIdx.x, lane = tid & 31, wid = tid >> 5;
    const int r = lane >> 2, cc = lane & 3;
    const int wm = (wid & 1) * 64, wn = (wid >> 1) * 32;
    const int m0 = blockIdx.x * 128;

    #pragma unroll
    for (int i = 0; i < 4; i++) {
        int idx = tid + i * 256;
        int row = idx >> 3, chk = idx & 7;
        cp16(Zb + (row * 72 + chk * 8) * 2, zeh + (size_t)(m0 + row) * 64 + chk * 8);
    }
    CP_COMMIT();

    #define ESTAGE(buf, chunk) do { \
        _Pragma("unroll") \
        for (int i = 0; i < 4; i++) { \
            int idx = tid + i * 256; \
            int row = idx >> 3, chk = idx & 7; \
            cp16(Eb + ((buf) * 9216 + row * 72 + chk * 8) * 2, \
                 embh + (size_t)((chunk) * 128 + row) * 64 + chk * 8); \
        } \
        CP_COMMIT(); \
    } while (0)

    ESTAGE(0, 0);
    ESTAGE(1, 1);

    float bv[8][4]; int bi[8][4];
    #pragma unroll
    for (int i = 0; i < 8; i++)
        #pragma unroll
        for (int j = 0; j < 4; j++) { bv[i][j] = 3.4e38f; bi[i][j] = 0; }

    for (int ch = 0; ch < 64; ch++) {
        const int buf = ch & 1;
        if (ch + 1 < 64) CP_WAIT1(); else CP_WAIT0();
        __syncthreads();

        float acc[4][4][4];
        const __half* Ef = Es + buf * 9216;
        #pragma unroll
        for (int ks = 0; ks < 4; ks++) {
            u32 a[4][4], b[4][2];
            #pragma unroll
            for (int mt = 0; mt < 4; mt++) {
                const __half* p = Zs + (wm + mt * 16 + r) * 72 + ks * 16 + 2 * cc;
                a[mt][0] = *reinterpret_cast<const u32*>(p);
                a[mt][1] = *reinterpret_cast<const u32*>(p + 8 * 72);
                a[mt][2] = *reinterpret_cast<const u32*>(p + 8);
                a[mt][3] = *reinterpret_cast<const u32*>(p + 8 * 72 + 8);
            }
            #pragma unroll
            for (int nt = 0; nt < 4; nt++) {
                const __half* q = Ef + (wn + nt * 8 + r) * 72 + ks * 16 + 2 * cc;
                b[nt][0] = *reinterpret_cast<const u32*>(q);
                b[nt][1] = *reinterpret_cast<const u32*>(q + 8);
            }
            if (ks == 0) {
                #pragma unroll
                for (int mt = 0; mt < 4; mt++)
                    #pragma unroll
                    for (int nt = 0; nt < 4; nt++)
                        MMA_F16_Z(acc[mt][nt], a[mt], b[nt]);
            } else {
                #pragma unroll
                for (int mt = 0; mt < 4; mt++)
                    #pragma unroll
                    for (int nt = 0; nt < 4; nt++)
                        MMA_F16(acc[mt][nt], a[mt], b[nt]);
            }
        }

        const int c0 = ch * 128;
        #pragma unroll
        for (int nt = 0; nt < 4; nt++) {
            int cbase = c0 + wn + nt * 8 + 2 * cc;
            float2 en = *reinterpret_cast<const float2*>(&enorm[cbase]);
            #pragma unroll
            for (int mt = 0; mt < 4; mt++) {
                #pragma unroll
                for (int j = 0; j < 4; j++) {
                    float d = fmaf(-2.f, acc[mt][nt][j], (j & 1) ? en.y : en.x);
                    int code = cbase + (j & 1);
                    int rr = mt * 2 + (j >> 1);
                    if (d < bv[rr][3]) {
                        if (d < bv[rr][1]) {
                            bv[rr][3] = bv[rr][2]; bi[rr][3] = bi[rr][2];
                            bv[rr][2] = bv[rr][1]; bi[rr][2] = bi[rr][1];
                            if (d < bv[rr][0]) {
                                bv[rr][1] = bv[rr][0]; bi[rr][1] = bi[rr][0];
                                bv[rr][0] = d; bi[rr][0] = code;
                            } else { bv[rr][1] = d; bi[rr][1] = code; }
                        } else {
                            if (d < bv[rr][2]) {
                                bv[rr][3] = bv[rr][2]; bi[rr][3] = bi[rr][2];
                                bv[rr][2] = d; bi[rr][2] = code;
                            } else { bv[rr][3] = d; bi[rr][3] = code; }
                        }
                    }
                }
            }
        }
        __syncthreads();
        if (ch + 2 < 64) ESTAGE(buf, ch + 2);
    }
    #undef ESTAGE

    const int sbase = ((wid >> 1) * 4 + cc) * 4;
    #pragma unroll
    for (int rr = 0; rr < 8; rr++) {
        int row = m0 + wm + (rr >> 1) * 16 + r + (rr & 1) * 8;
        *reinterpret_cast<int4*>(&cand[(size_t)row * 64 + sbase]) =
            make_int4(bi[rr][0], bi[rr][1], bi[rr][2], bi[rr][3]);
    }
}

// ---------------------------------------------------------------------------
// Phase 2: exact fp32 rescore + fused z_q write
// ---------------------------------------------------------------------------
__global__ void __launch_bounds__(256)
rescore_kernel(const float* __restrict__ ze, const float* __restrict__ emb,
               const float* __restrict__ enorm, const int* __restrict__ cand,
               int* __restrict__ out_idx, float* __restrict__ zq)
{
    __shared__ float sred[4][2];
    __shared__ int   sidx[4][2];
    __shared__ int   swin[4];
    const int tid = threadIdx.x;
    const int rowloc = tid >> 6, l = tid & 63, lane = tid & 31;
    const int row = blockIdx.x * 4 + rowloc;

    int c = cand[(size_t)row * 64 + l];
    const float4* zp = reinterpret_cast<const float4*>(ze + (size_t)row * 64);
    const float4* ep = reinterpret_cast<const float4*>(emb + (size_t)c * 64);
    float s = 0.f;
    #pragma unroll
    for (int q = 0; q < 16; q++) {
        float4 z4 = zp[q], e4 = ep[q];
        s = fmaf(z4.x, e4.x, s); s = fmaf(z4.y, e4.y, s);
        s = fmaf(z4.z, e4.z, s); s = fmaf(z4.w, e4.w, s);
    }
    float d = fmaf(-2.f, s, enorm[c]);

    #pragma unroll
    for (int off = 16; off; off >>= 1) {
        float od = __shfl_xor_sync(0xffffffffu, d, off);
        int   oc = __shfl_xor_sync(0xffffffffu, c, off);
        if (od < d || (od == d && oc < c)) { d = od; c = oc; }
    }
    const int wl = (tid >> 5) & 1;
    if (lane == 0) { sred[rowloc][wl] = d; sidx[rowloc][wl] = c; }
    __syncthreads();
    if (l == 0) {
        float d0 = sred[rowloc][0], d1 = sred[rowloc][1];
        int   i0 = sidx[rowloc][0], i1 = sidx[rowloc][1];
        int win = (d1 < d0 || (d1 == d0 && i1 < i0)) ? i1 : i0;
        out_idx[row] = win;
        swin[rowloc] = win;
    }
    __syncthreads();
    int wc = swin[rowloc];
    zq[(size_t)row * 64 + l] = emb[(size_t)wc * 64 + l];
}

// ---- FFMA SGEMM; ACT: 0 none(float out), 4 relu + fp16 out ------------------
template<int BM, int BN, int BK, int ACT>
__global__ void __launch_bounds__((BM/8)*(BN/8))
sgemm_bias_act(const float* __restrict__ A, const float* __restrict__ W,
               const float* __restrict__ bias, float* __restrict__ C,
               int M, int N, int Kd)
{
    constexpr int TM = 8, TN = 8;
    constexpr int THREADS = (BM/TM) * (BN/TN);
    __shared__ __align__(16) float Ash[BK][BM];
    __shared__ __align__(16) float Wsh[BK][BN];

    const int tid = threadIdx.x;
    const int tx = tid % (BN/TN), ty = tid / (BN/TN);
    const int m0 = blockIdx.y * BM, n0 = blockIdx.x * BN;

    u64 acc[TM][TN/2];
    #pragma unroll
    for (int i = 0; i < TM; i++)
        #pragma unroll
        for (int j = 0; j < TN/2; j++) acc[i][j] = 0ull;

    for (int k0 = 0; k0 < Kd; k0 += BK) {
        constexpr int AV = (BM * BK) / (THREADS * 4);
        #pragma unroll
        for (int it = 0; it < AV; ++it) {
            int li = tid + it * THREADS;
            int m = li / (BK/4), kq = li % (BK/4);
            float4 v = *reinterpret_cast<const float4*>(&A[(size_t)(m0 + m) * Kd + k0 + kq*4]);
            Ash[kq*4+0][m] = v.x; Ash[kq*4+1][m] = v.y;
            Ash[kq*4+2][m] = v.z; Ash[kq*4+3][m] = v.w;
        }
        constexpr int WV = (BK * BN) / (THREADS * 4);
        #pragma unroll
        for (int it = 0; it < WV; ++it) {
            int li = tid + it * THREADS;
            int k = li / (BN/4), nq = li % (BN/4);
            int n = n0 + nq*4;
            float4 v = make_float4(0.f, 0.f, 0.f, 0.f);
            if (n < N) v = *reinterpret_cast<const float4*>(&W[(size_t)(k0 + k) * N + n]);
            *reinterpret_cast<float4*>(&Wsh[k][nq*4]) = v;
        }
        __syncthreads();
        #pragma unroll
        for (int k = 0; k < BK; k++) {
            float4 a0 = *reinterpret_cast<const float4*>(&Ash[k][ty*TM]);
            float4 a1 = *reinterpret_cast<const float4*>(&Ash[k][ty*TM + 4]);
            float a[TM] = {a0.x, a0.y, a0.z, a0.w, a1.x, a1.y, a1.z, a1.w};
            const u64* wr = reinterpret_cast<const u64*>(&Wsh[k][tx*TN]);
            u64 b2[TN/2];
            #pragma unroll
            for (int j = 0; j < TN/2; j++) b2[j] = wr[j];
            #pragma unroll
            for (int i = 0; i < TM; i++) {
                u64 ad = pack2(a[i], a[i]);
                #pragma unroll
                for (int j = 0; j < TN/2; j++) fma2(acc[i][j], ad, b2[j]);
            }
        }
        __syncthreads();
    }
    #pragma unroll
    for (int i = 0; i < TM; i++) {
        int m = m0 + ty*TM + i;
        #pragma unroll
        for (int j = 0; j < TN/2; j++) {
            int n = n0 + tx*TN + j*2;
            if (n < N) {
                float lo, hi; unpack2(acc[i][j], lo, hi);
                lo += bias[n]; hi += bias[n+1];
                if (ACT == 4) {
                    lo = fmaxf(lo, 0.f); hi = fmaxf(hi, 0.f);
                    __half* Ch = reinterpret_cast<__half*>(C);
                    *reinterpret_cast<__half2*>(&Ch[(size_t)m * N + n]) =
                        __floats2half2_rn(lo, hi);
                } else {
                    *reinterpret_cast<float2*>(&C[(size_t)m * N + n]) = make_float2(lo, hi);
                }
            }
        }
    }
}

// ---- emb norms --------------------------------------------------------------
__global__ void emb_norms_kernel(const float* __restrict__ emb, float* __restrict__ enorm)
{
    int g = (blockIdx.x * blockDim.x + threadIdx.x) >> 5;
    int lane = threadIdx.x & 31;
    if (g >= NK) return;
    float a = emb[(size_t)g * 64 + lane];
    float b = emb[(size_t)g * 64 + 32 + lane];
    float s = a*a + b*b;
    #pragma unroll
    for (int off = 16; off; off >>= 1) s += __shfl_xor_sync(0xffffffffu, s, off);
    if (lane == 0) enorm[g] = s;
}

// ---------------------------------------------------------------------------
extern "C" void kernel_launch(void* const* d_in, const int* in_sizes, int n_in,
                              void* d_out, int out_size)
{
    const float* x   = (const float*)d_in[0];
    const float* W1  = (const float*)d_in[1];
    const float* b1  = (const float*)d_in[2];
    const float* W2  = (const float*)d_in[3];
    const float* b2  = (const float*)d_in[4];
    const float* W3  = (const float*)d_in[5];
    const float* b3  = (const float*)d_in[6];
    const float* W4  = (const float*)d_in[7];
    const float* b4  = (const float*)d_in[8];
    const float* emb = (const float*)d_in[9];

    float* out     = (float*)d_out;
    float* x_recon = out;
    float* z_e     = out + (size_t)NB * DIN;
    float* z_q     = z_e + (size_t)NB * DLAT;

    float *h1, *enorm; __half *h2, *H3, *a3h, *w1th, *w4t, *embh, *zeh; int *idxp, *candp;
    cudaGetSymbolAddress((void**)&h1, g_h1);
    cudaGetSymbolAddress((void**)&h2, g_h2);
    cudaGetSymbolAddress((void**)&H3, g_H3);
    cudaGetSymbolAddress((void**)&a3h, g_a3h);
    cudaGetSymbolAddress((void**)&w1th, g_w1th);
    cudaGetSymbolAddress((void**)&w4t, g_w4t);
    cudaGetSymbolAddress((void**)&embh, g_emb_h);
    cudaGetSymbolAddress((void**)&zeh, g_ze_h);
    cudaGetSymbolAddress((void**)&enorm, g_enorm);
    cudaGetSymbolAddress((void**)&idxp, g_idx);
    cudaGetSymbolAddress((void**)&candp, g_cand);

    cudaFuncSetAttribute(hmma_gemm<1>, cudaFuncAttributeMaxDynamicSharedMemorySize, MMA_SMEM);
    cudaFuncSetAttribute(hmma_gemm<2>, cudaFuncAttributeMaxDynamicSharedMemorySize, MMA_SMEM);
    cudaFuncSetAttribute(cand_kernel_h, cudaFuncAttributeMaxDynamicSharedMemorySize, CAND_SMEM_H);

    emb_norms_kernel<<<NK/8, 256>>>(emb, enorm);
    f2h_kernel<<<(NK*DLAT/4 + 255)/256, 256>>>((const float4*)emb, (__half2*)embh, NK*DLAT/4);
    {   size_t tot = (size_t)DH * KP1;
        split3_WT_h<<<(unsigned)((tot + 255)/256), 256>>>(W1, w1th, DIN, DH, DH, KP1); }
    {   size_t tot = (size_t)NPAD4 * KP4;
        round_WT_h<<<(unsigned)((tot + 255)/256), 256>>>(W4, w4t, DH, DIN, NPAD4); }

    // H3[c] = half(relu(emb[c] @ W3 + b3)) over 8192 codes
    sgemm_bias_act<128,128,16,4><<<dim3(DH/128, NK/128), 256>>>(
        emb, W3, b3, (float*)H3, NK, DH, DLAT);

    {   size_t tot = (size_t)NB * (DIN/4);
        split3_A_h<<<(unsigned)((tot + 255)/256), 256>>>(x, a3h, DIN, KP1);
        size_t tt = (size_t)NB * (KP1 - 3*DIN);
        zero_tail_A_h<<<(unsigned)((tt + 255)/256), 256>>>(a3h, 3*DIN, KP1); }

    // h1 = relu((x @ 64*W1)/64 + b1)   [3xFP16 split — argmin-safe, proven]
    hmma_gemm<1><<<dim3(DH/128, NB/128), 256, MMA_SMEM>>>(
        a3h, w1th, b1, h1, KP1, DH, INV_WSCALE);

    // z_e = h1 @ W2 + b2  (exact fp32 FFMA — small-N GEMM stays scalar)
    sgemm_bias_act<128,64,16,0><<<dim3(1, NB/128), 128>>>(h1, W2, b2, z_e, NB, DLAT, DH);

    // z_e -> fp16 for approx phase
    f2h_kernel<<<(NB*DLAT/4 + 255)/256, 256>>>((const float4*)z_e, (__half2*)zeh, NB*DLAT/4);

    // argmin: fp16 approx tensor phase + exact fp32 rescore (+ fused z_q write)
    cand_kernel_h<<<NB/128, 256, CAND_SMEM_H>>>(zeh, embh, enorm, candp);
    rescore_kernel<<<NB/4, 256>>>(z_e, emb, enorm, candp, idxp, z_q);

    // h2[m] = H3[idx[m]]  (row-copy gather)
    gather_h2_kernel<<<(unsigned)(((size_t)NB*128 + 255)/256), 256>>>(idxp, H3, h2);

    // x_recon = sigmoid(h2 @ W4 + b4)
    hmma_gemm<2><<<dim3(NPAD4/128, NB/128), 256, MMA_SMEM>>>(
        h2, w4t, b4, x_recon, KP4, DIN, 1.0f);
}

// round 16
// speedup vs baseline: 1.0909x; 1.0005x over previous
#include <cuda_runtime.h>
#include <cuda_fp16.h>
#include <math.h>
#include <stdint.h>

#define NB 32768
#define DIN 784
#define DH 1024
#define DLAT 64
#define NK 8192
#define KP1 2368   // 3*784=2352 padded to 64-multiple
#define KP4 1024
#define NPAD4 896
#define WSCALE 64.0f
#define INV_WSCALE (1.0f / 64.0f)

typedef unsigned long long u64;
typedef unsigned int u32;

__device__ float  g_h1[(size_t)NB * DH];
__device__ __half g_h2[(size_t)NB * DH];
__device__ __half g_H3[(size_t)NK * DH];      // per-code decoder hidden (16 MB)
__device__ __half g_a3h[(size_t)NB * KP1];
__device__ __half g_w1th[(size_t)DH * KP1];
__device__ __half g_w4t[(size_t)NPAD4 * KP4];
__device__ __half g_emb_h[(size_t)NK * DLAT];
__device__ __half g_ze_h[(size_t)NB * DLAT];
__device__ float  g_enorm[NK];
__device__ int    g_idx[NB];
__device__ int    g_cand[(size_t)NB * 64];

__device__ __forceinline__ u64 pack2(float lo, float hi) {
    u64 r; asm("mov.b64 %0, {%1,%2};" : "=l"(r) : "f"(lo), "f"(hi)); return r;
}
__device__ __forceinline__ void unpack2(u64 v, float& lo, float& hi) {
    asm("mov.b64 {%0,%1}, %2;" : "=f"(lo), "=f"(hi) : "l"(v));
}
__device__ __forceinline__ void fma2(u64& acc, u64 a, u64 b) {
    asm("fma.rn.f32x2 %0, %1, %2, %0;" : "+l"(acc) : "l"(a), "l"(b));
}
__device__ __forceinline__ u32 smem_u32(const void* p) {
    u32 a;
    asm("{ .reg .u64 t; cvta.to.shared.u64 t, %1; cvt.u32.u64 %0, t; }" : "=r"(a) : "l"(p));
    return a;
}
__device__ __forceinline__ void cp16(u32 dst, const void* src) {
    asm volatile("cp.async.cg.shared.global [%0], [%1], 16;" :: "r"(dst), "l"(src));
}
#define CP_COMMIT() asm volatile("cp.async.commit_group;" ::: "memory")
#define CP_WAIT1()  asm volatile("cp.async.wait_group 1;" ::: "memory")
#define CP_WAIT0()  asm volatile("cp.async.wait_group 0;" ::: "memory")

__device__ __forceinline__ void ldsm_x4(u32& r0, u32& r1, u32& r2, u32& r3, u32 addr) {
    asm volatile("ldmatrix.sync.aligned.m8n8.x4.shared.b16 {%0,%1,%2,%3}, [%4];"
        : "=r"(r0), "=r"(r1), "=r"(r2), "=r"(r3) : "r"(addr));
}

#define MMA_F16(acc, a0, a1, a2, a3, b0, b1) \
    asm volatile( \
        "mma.sync.aligned.m16n8k16.row.col.f32.f16.f16.f32 " \
        "{%0,%1,%2,%3}, {%4,%5,%6,%7}, {%8,%9}, {%0,%1,%2,%3};" \
        : "+f"((acc)[0]), "+f"((acc)[1]), "+f"((acc)[2]), "+f"((acc)[3]) \
        : "r"(a0), "r"(a1), "r"(a2), "r"(a3), "r"(b0), "r"(b1))

#define MMA_F16A(acc, a, b) \
    asm volatile( \
        "mma.sync.aligned.m16n8k16.row.col.f32.f16.f16.f32 " \
        "{%0,%1,%2,%3}, {%4,%5,%6,%7}, {%8,%9}, {%0,%1,%2,%3};" \
        : "+f"((acc)[0]), "+f"((acc)[1]), "+f"((acc)[2]), "+f"((acc)[3]) \
        : "r"((a)[0]), "r"((a)[1]), "r"((a)[2]), "r"((a)[3]), \
          "r"((b)[0]), "r"((b)[1]))

#define MMA_F16A_Z(acc, a, b) \
    asm volatile( \
        "mma.sync.aligned.m16n8k16.row.col.f32.f16.f16.f32 " \
        "{%0,%1,%2,%3}, {%4,%5,%6,%7}, {%8,%9}, {%10,%10,%10,%10};" \
        : "=f"((acc)[0]), "=f"((acc)[1]), "=f"((acc)[2]), "=f"((acc)[3]) \
        : "r"((a)[0]), "r"((a)[1]), "r"((a)[2]), "r"((a)[3]), \
          "r"((b)[0]), "r"((b)[1]), "f"(0.f))

// ---- prep kernels -----------------------------------------------------------
__global__ void split3_A_h(const float* __restrict__ in, __half* __restrict__ out,
                           int K, int KP)
{
    size_t t = blockIdx.x * (size_t)blockDim.x + threadIdx.x;
    if (t >= (size_t)NB * (K / 4)) return;
    int m = (int)(t / (K / 4));
    int kq = (int)(t % (K / 4)) * 4;
    float4 v = *reinterpret_cast<const float4*>(&in[(size_t)m * K + kq]);
    __half hx = __float2half_rn(v.x), hy = __float2half_rn(v.y);
    __half hz = __float2half_rn(v.z), hw = __float2half_rn(v.w);
    __half2 hi0 = __halves2half2(hx, hy), hi1 = __halves2half2(hz, hw);
    __half2 lo0 = __floats2half2_rn(v.x - __half2float(hx), v.y - __half2float(hy));
    __half2 lo1 = __floats2half2_rn(v.z - __half2float(hz), v.w - __half2float(hw));
    __half* o = &out[(size_t)m * KP1];
    *reinterpret_cast<__half2*>(&o[kq])             = hi0;
    *reinterpret_cast<__half2*>(&o[kq + 2])         = hi1;
    *reinterpret_cast<__half2*>(&o[K + kq])         = lo0;
    *reinterpret_cast<__half2*>(&o[K + kq + 2])     = lo1;
    *reinterpret_cast<__half2*>(&o[2 * K + kq])     = hi0;
    *reinterpret_cast<__half2*>(&o[2 * K + kq + 2]) = hi1;
}

__global__ void zero_tail_A_h(__half* __restrict__ out, int K3, int KP)
{
    int w = KP - K3;
    size_t t = blockIdx.x * (size_t)blockDim.x + threadIdx.x;
    if (t >= (size_t)NB * w) return;
    out[(size_t)(t / w) * KP + K3 + (int)(t % w)] = __float2half_rn(0.f);
}

// W split (scaled by WSCALE): out[n, kp] = [ w_hi | w_hi | w_lo ], tail zero
__global__ void split3_WT_h(const float* __restrict__ W, __half* __restrict__ out,
                            int K, int N, int NA, int KP)
{
    size_t t = blockIdx.x * (size_t)blockDim.x + threadIdx.x;
    if (t >= (size_t)NA * KP) return;
    int n = (int)(t / KP);
    int kp = (int)(t % KP);
    float val = 0.0f;
    if (n < N) {
        if (kp < K) {
            val = __half2float(__float2half_rn(W[(size_t)kp * N + n] * WSCALE));
        } else if (kp < 2 * K) {
            val = __half2float(__float2half_rn(W[(size_t)(kp - K) * N + n] * WSCALE));
        } else if (kp < 3 * K) {
            float a = W[(size_t)(kp - 2 * K) * N + n] * WSCALE;
            val = a - __half2float(__float2half_rn(a));
        }
    }
    out[t] = __float2half_rn(val);
}

__global__ void round_WT_h(const float* __restrict__ W, __half* __restrict__ out,
                           int K, int N, int NA)
{
    size_t t = blockIdx.x * (size_t)blockDim.x + threadIdx.x;
    if (t >= (size_t)NA * K) return;
    int n = (int)(t / K);
    int k = (int)(t % K);
    out[t] = (n < N) ? __float2half_rn(W[(size_t)k * N + n]) : __float2half_rn(0.f);
}

__global__ void f2h_kernel(const float4* __restrict__ in, __half2* __restrict__ out, int n4)
{
    int t = blockIdx.x * blockDim.x + threadIdx.x;
    if (t >= n4) return;
    float4 v = in[t];
    out[2 * t + 0] = __floats2half2_rn(v.x, v.y);
    out[2 * t + 1] = __floats2half2_rn(v.z, v.w);
}

// row-copy gather: h2[m] = H3[idx[m]]  (int4 = 8 halves/thread)
__global__ void gather_h2_kernel(const int* __restrict__ idx,
                                 const __half* __restrict__ H3, __half* __restrict__ h2)
{
    size_t t = blockIdx.x * (size_t)blockDim.x + threadIdx.x;   // NB*128
    int m = (int)(t >> 7), q = (int)(t & 127);
    const int4* src = reinterpret_cast<const int4*>(H3 + (size_t)idx[m] * DH);
    reinterpret_cast<int4*>(h2 + (size_t)m * DH)[q] = src[q];
}

// ---------------------------------------------------------------------------
// FP16 tensor-core GEMM: C[M,Nout] = act(scale * (A[M,K]h @ WT[:,K]h^T) + bias)
// 128x128 tile, BK=64, m16n8k16, cp.async double-buffered, stride 72 halves.
// Fragment loads via ldmatrix.x4 (6 instr/ks instead of 24 LDS.32).
// ACT: 1 = relu (float out), 2 = sigmoid (float out)
// ---------------------------------------------------------------------------
#define MMA_SMEM (2 * 128 * 72 * 2 * 2)   // 73728 bytes

template<int ACT>
__global__ void __launch_bounds__(256)
hmma_gemm(const __half* __restrict__ A, const __half* __restrict__ WT,
          const float* __restrict__ bias, float* __restrict__ C,
          int K, int Nout, float scale)
{
    extern __shared__ __half smh[];
    __half* As = smh;                   // [2][128][72]
    __half* Bs = smh + 2 * 128 * 72;
    const u32 As_b = smem_u32(As), Bs_b = smem_u32(Bs);

    const int tid = threadIdx.x, lane = tid & 31, wid = tid >> 5;
    const int wm = (wid & 1) * 64, wn = (wid >> 1) * 32;
    const int m0 = blockIdx.y * 128, n0 = blockIdx.x * 128;

    float acc[4][4][4];
    #pragma unroll
    for (int i = 0; i < 4; i++)
        #pragma unroll
        for (int j = 0; j < 4; j++)
            #pragma unroll
            for (int k = 0; k < 4; k++) acc[i][j][k] = 0.f;

    const int nkb = K / 64;
    const __half* Ag = A + (size_t)m0 * K;
    const __half* Bg = WT + (size_t)n0 * K;
    const int srow = tid >> 3, skq = tid & 7;

    // ldmatrix per-thread fragment offsets (bytes; row stride = 144 B)
    const int lane7 = lane & 7;
    const u32 a_frag = (u32)(((lane7 + ((lane >> 3) & 1) * 8) + wm) * 144
                             + ((lane >> 4) & 1) * 16);
    const u32 b_frag = (u32)(((((lane >> 4) & 1) * 8 + lane7) + wn) * 144
                             + ((lane >> 3) & 1) * 16);

    #define HSTAGE(buf, kb) do { \
        _Pragma("unroll") \
        for (int i = 0; i < 4; i++) { \
            int row = srow + i * 32; \
            cp16(As_b + ((buf) * 9216 + row * 72 + skq * 8) * 2, \
                 Ag + (size_t)row * K + (kb) * 64 + skq * 8); \
        } \
        _Pragma("unroll") \
        for (int i = 0; i < 4; i++) { \
            int row = srow + i * 32; \
            cp16(Bs_b + ((buf) * 9216 + row * 72 + skq * 8) * 2, \
                 Bg + (size_t)row * K + (kb) * 64 + skq * 8); \
        } \
        CP_COMMIT(); \
    } while (0)

    HSTAGE(0, 0);
    HSTAGE(1, 1);

    const int r = lane >> 2, cc = lane & 3;

    for (int kb = 0; kb < nkb; kb++) {
        const int buf = kb & 1;
        if (kb + 1 < nkb) CP_WAIT1(); else CP_WAIT0();
        __syncthreads();

        const u32 Ab = As_b + buf * 18432 + a_frag;
        const u32 Bb = Bs_b + buf * 18432 + b_frag;
        #pragma unroll
        for (int ks = 0; ks < 4; ks++) {
            u32 a[4][4], b2[2][4];
            #pragma unroll
            for (int mt = 0; mt < 4; mt++)
                ldsm_x4(a[mt][0], a[mt][1], a[mt][2], a[mt][3],
                        Ab + mt * (16 * 144) + ks * 32);
            #pragma unroll
            for (int p = 0; p < 2; p++)
                ldsm_x4(b2[p][0], b2[p][1], b2[p][2], b2[p][3],
                        Bb + p * (16 * 144) + ks * 32);
            #pragma unroll
            for (int mt = 0; mt < 4; mt++)
                #pragma unroll
                for (int nt = 0; nt < 4; nt++)
                    MMA_F16(acc[mt][nt],
                            a[mt][0], a[mt][1], a[mt][2], a[mt][3],
                            b2[nt >> 1][(nt & 1) * 2], b2[nt >> 1][(nt & 1) * 2 + 1]);
        }
        __syncthreads();
        if (kb + 2 < nkb) HSTAGE(buf, kb + 2);
    }
    #undef HSTAGE

    #pragma unroll
    for (int mt = 0; mt < 4; mt++) {
        int row0 = m0 + wm + mt * 16 + r;
        #pragma unroll
        for (int nt = 0; nt < 4; nt++) {
            int col = n0 + wn + nt * 8 + 2 * cc;
            if (col < Nout) {
                float bx = bias[col], by = bias[col + 1];
                float v0 = fmaf(acc[mt][nt][0], scale, bx);
                float v1 = fmaf(acc[mt][nt][1], scale, by);
                float v2 = fmaf(acc[mt][nt][2], scale, bx);
                float v3 = fmaf(acc[mt][nt][3], scale, by);
                if (ACT == 1) {
                    v0 = fmaxf(v0, 0.f); v1 = fmaxf(v1, 0.f);
                    v2 = fmaxf(v2, 0.f); v3 = fmaxf(v3, 0.f);
                } else {
                    v0 = 1.f / (1.f + expf(-v0)); v1 = 1.f / (1.f + expf(-v1));
                    v2 = 1.f / (1.f + expf(-v2)); v3 = 1.f / (1.f + expf(-v3));
                }
                *reinterpret_cast<float2*>(&C[(size_t)row0 * Nout + col]) = make_float2(v0, v1);
                *reinterpret_cast<float2*>(&C[(size_t)(row0 + 8) * Nout + col]) = make_float2(v2, v3);
            }
        }
    }
}

// ---------------------------------------------------------------------------
// Phase 1 (fp16): approx distances, top-4 candidates per (thread,row) (proven)
// ---------------------------------------------------------------------------
#define CAND_SMEM_H (3 * 128 * 72 * 2)   // 55296 bytes

__global__ void __launch_bounds__(256)
cand_kernel_h(const __half* __restrict__ zeh, const __half* __restrict__ embh,
              const float* __restrict__ enorm, int* __restrict__ cand)
{
    extern __shared__ __half smh[];
    __half* Zs = smh;                    // [128][72]
    __half* Es = smh + 128 * 72;         // [2][128][72]
    const u32 Zb = smem_u32(Zs), Eb = smem_u32(Es);

    const int tid = threadIdx.x, lane = tid & 31, wid = tid >> 5;
    const int r = lane >> 2, cc = lane & 3;
    const int wm = (wid & 1) * 64, wn = (wid >> 1) * 32;
    const int m0 = blockIdx.x * 128;

    #pragma unroll
    for (int i = 0; i < 4; i++) {
        int idx = tid + i * 256;
        int row = idx >> 3, chk = idx & 7;
        cp16(Zb + (row * 72 + chk * 8) * 2, zeh + (size_t)(m0 + row) * 64 + chk * 8);
    }
    CP_COMMIT();

    #define ESTAGE(buf, chunk) do { \
        _Pragma("unroll") \
        for (int i = 0; i < 4; i++) { \
            int idx = tid + i * 256; \
            int row = idx >> 3, chk = idx & 7; \
            cp16(Eb + ((buf) * 9216 + row * 72 + chk * 8) * 2, \
                 embh + (size_t)((chunk) * 128 + row) * 64 + chk * 8); \
        } \
        CP_COMMIT(); \
    } while (0)

    ESTAGE(0, 0);
    ESTAGE(1, 1);

    float bv[8][4]; int bi[8][4];
    #pragma unroll
    for (int i = 0; i < 8; i++)
        #pragma unroll
        for (int j = 0; j < 4; j++) { bv[i][j] = 3.4e38f; bi[i][j] = 0; }

    for (int ch = 0; ch < 64; ch++) {
        const int buf = ch & 1;
        if (ch + 1 < 64) CP_WAIT1(); else CP_WAIT0();
        __syncthreads();

        float acc[4][4][4];
        const __half* Ef = Es + buf * 9216;
        #pragma unroll
        for (int ks = 0; ks < 4; ks++) {
            u32 a[4][4], b[4][2];
            #pragma unroll
            for (int mt = 0; mt < 4; mt++) {
                const __half* p = Zs + (wm + mt * 16 + r) * 72 + ks * 16 + 2 * cc;
                a[mt][0] = *reinterpret_cast<const u32*>(p);
                a[mt][1] = *reinterpret_cast<const u32*>(p + 8 * 72);
                a[mt][2] = *reinterpret_cast<const u32*>(p + 8);
                a[mt][3] = *reinterpret_cast<const u32*>(p + 8 * 72 + 8);
            }
            #pragma unroll
            for (int nt = 0; nt < 4; nt++) {
                const __half* q = Ef + (wn + nt * 8 + r) * 72 + ks * 16 + 2 * cc;
                b[nt][0] = *reinterpret_cast<const u32*>(q);
                b[nt][1] = *reinterpret_cast<const u32*>(q + 8);
            }
            if (ks == 0) {
                #pragma unroll
                for (int mt = 0; mt < 4; mt++)
                    #pragma unroll
                    for (int nt = 0; nt < 4; nt++)
                        MMA_F16A_Z(acc[mt][nt], a[mt], b[nt]);
            } else {
                #pragma unroll
                for (int mt = 0; mt < 4; mt++)
                    #pragma unroll
                    for (int nt = 0; nt < 4; nt++)
                        MMA_F16A(acc[mt][nt], a[mt], b[nt]);
            }
        }

        const int c0 = ch * 128;
        #pragma unroll
        for (int nt = 0; nt < 4; nt++) {
            int cbase = c0 + wn + nt * 8 + 2 * cc;
            float2 en = *reinterpret_cast<const float2*>(&enorm[cbase]);
            #pragma unroll
            for (int mt = 0; mt < 4; mt++) {
                #pragma unroll
                for (int j = 0; j < 4; j++) {
                    float d = fmaf(-2.f, acc[mt][nt][j], (j & 1) ? en.y : en.x);
                    int code = cbase + (j & 1);
                    int rr = mt * 2 + (j >> 1);
                    if (d < bv[rr][3]) {
                        if (d < bv[rr][1]) {
                            bv[rr][3] = bv[rr][2]; bi[rr][3] = bi[rr][2];
                            bv[rr][2] = bv[rr][1]; bi[rr][2] = bi[rr][1];
                            if (d < bv[rr][0]) {
                                bv[rr][1] = bv[rr][0]; bi[rr][1] = bi[rr][0];
                                bv[rr][0] = d; bi[rr][0] = code;
                            } else { bv[rr][1] = d; bi[rr][1] = code; }
                        } else {
                            if (d < bv[rr][2]) {
                                bv[rr][3] = bv[rr][2]; bi[rr][3] = bi[rr][2];
                                bv[rr][2] = d; bi[rr][2] = code;
                            } else { bv[rr][3] = d; bi[rr][3] = code; }
                        }
                    }
                }
            }
        }
        __syncthreads();
        if (ch + 2 < 64) ESTAGE(buf, ch + 2);
    }
    #undef ESTAGE

    const int sbase = ((wid >> 1) * 4 + cc) * 4;
    #pragma unroll
    for (int rr = 0; rr < 8; rr++) {
        int row = m0 + wm + (rr >> 1) * 16 + r + (rr & 1) * 8;
        *reinterpret_cast<int4*>(&cand[(size_t)row * 64 + sbase]) =
            make_int4(bi[rr][0], bi[rr][1], bi[rr][2], bi[rr][3]);
    }
}

// ---------------------------------------------------------------------------
// Phase 2: exact fp32 rescore + fused z_q write (proven)
// ---------------------------------------------------------------------------
__global__ void __launch_bounds__(256)
rescore_kernel(const float* __restrict__ ze, const float* __restrict__ emb,
               const float* __restrict__ enorm, const int* __restrict__ cand,
               int* __restrict__ out_idx, float* __restrict__ zq)
{
    __shared__ float sred[4][2];
    __shared__ int   sidx[4][2];
    __shared__ int   swin[4];
    const int tid = threadIdx.x;
    const int rowloc = tid >> 6, l = tid & 63, lane = tid & 31;
    const int row = blockIdx.x * 4 + rowloc;

    int c = cand[(size_t)row * 64 + l];
    const float4* zp = reinterpret_cast<const float4*>(ze + (size_t)row * 64);
    const float4* ep = reinterpret_cast<const float4*>(emb + (size_t)c * 64);
    float s = 0.f;
    #pragma unroll
    for (int q = 0; q < 16; q++) {
        float4 z4 = zp[q], e4 = ep[q];
        s = fmaf(z4.x, e4.x, s); s = fmaf(z4.y, e4.y, s);
        s = fmaf(z4.z, e4.z, s); s = fmaf(z4.w, e4.w, s);
    }
    float d = fmaf(-2.f, s, enorm[c]);

    #pragma unroll
    for (int off = 16; off; off >>= 1) {
        float od = __shfl_xor_sync(0xffffffffu, d, off);
        int   oc = __shfl_xor_sync(0xffffffffu, c, off);
        if (od < d || (od == d && oc < c)) { d = od; c = oc; }
    }
    const int wl = (tid >> 5) & 1;
    if (lane == 0) { sred[rowloc][wl] = d; sidx[rowloc][wl] = c; }
    __syncthreads();
    if (l == 0) {
        float d0 = sred[rowloc][0], d1 = sred[rowloc][1];
        int   i0 = sidx[rowloc][0], i1 = sidx[rowloc][1];
        int win = (d1 < d0 || (d1 == d0 && i1 < i0)) ? i1 : i0;
        out_idx[row] = win;
        swin[rowloc] = win;
    }
    __syncthreads();
    int wc = swin[rowloc];
    zq[(size_t)row * 64 + l] = emb[(size_t)wc * 64 + l];
}

// ---- FFMA SGEMM; ACT: 0 none(float out), 4 relu + fp16 out ------------------
template<int BM, int BN, int BK, int ACT>
__global__ void __launch_bounds__((BM/8)*(BN/8))
sgemm_bias_act(const float* __restrict__ A, const float* __restrict__ W,
               const float* __restrict__ bias, float* __restrict__ C,
               int M, int N, int Kd)
{
    constexpr int TM = 8, TN = 8;
    constexpr int THREADS = (BM/TM) * (BN/TN);
    __shared__ __align__(16) float Ash[BK][BM];
    __shared__ __align__(16) float Wsh[BK][BN];

    const int tid = threadIdx.x;
    const int tx = tid % (BN/TN), ty = tid / (BN/TN);
    const int m0 = blockIdx.y * BM, n0 = blockIdx.x * BN;

    u64 acc[TM][TN/2];
    #pragma unroll
    for (int i = 0; i < TM; i++)
        #pragma unroll
        for (int j = 0; j < TN/2; j++) acc[i][j] = 0ull;

    for (int k0 = 0; k0 < Kd; k0 += BK) {
        constexpr int AV = (BM * BK) / (THREADS * 4);
        #pragma unroll
        for (int it = 0; it < AV; ++it) {
            int li = tid + it * THREADS;
            int m = li / (BK/4), kq = li % (BK/4);
            float4 v = *reinterpret_cast<const float4*>(&A[(size_t)(m0 + m) * Kd + k0 + kq*4]);
            Ash[kq*4+0][m] = v.x; Ash[kq*4+1][m] = v.y;
            Ash[kq*4+2][m] = v.z; Ash[kq*4+3][m] = v.w;
        }
        constexpr int WV = (BK * BN) / (THREADS * 4);
        #pragma unroll
        for (int it = 0; it < WV; ++it) {
            int li = tid + it * THREADS;
            int k = li / (BN/4), nq = li % (BN/4);
            int n = n0 + nq*4;
            float4 v = make_float4(0.f, 0.f, 0.f, 0.f);
            if (n < N) v = *reinterpret_cast<const float4*>(&W[(size_t)(k0 + k) * N + n]);
            *reinterpret_cast<float4*>(&Wsh[k][nq*4]) = v;
        }
        __syncthreads();
        #pragma unroll
        for (int k = 0; k < BK; k++) {
            float4 a0 = *reinterpret_cast<const float4*>(&Ash[k][ty*TM]);
            float4 a1 = *reinterpret_cast<const float4*>(&Ash[k][ty*TM + 4]);
            float a[TM] = {a0.x, a0.y, a0.z, a0.w, a1.x, a1.y, a1.z, a1.w};
            const u64* wr = reinterpret_cast<const u64*>(&Wsh[k][tx*TN]);
            u64 b2[TN/2];
            #pragma unroll
            for (int j = 0; j < TN/2; j++) b2[j] = wr[j];
            #pragma unroll
            for (int i = 0; i < TM; i++) {
                u64 ad = pack2(a[i], a[i]);
                #pragma unroll
                for (int j = 0; j < TN/2; j++) fma2(acc[i][j], ad, b2[j]);
            }
        }
        __syncthreads();
    }
    #pragma unroll
    for (int i = 0; i < TM; i++) {
        int m = m0 + ty*TM + i;
        #pragma unroll
        for (int j = 0; j < TN/2; j++) {
            int n = n0 + tx*TN + j*2;
            if (n < N) {
                float lo, hi; unpack2(acc[i][j], lo, hi);
                lo += bias[n]; hi += bias[n+1];
                if (ACT == 4) {
                    lo = fmaxf(lo, 0.f); hi = fmaxf(hi, 0.f);
                    __half* Ch = reinterpret_cast<__half*>(C);
                    *reinterpret_cast<__half2*>(&Ch[(size_t)m * N + n]) =
                        __floats2half2_rn(lo, hi);
                } else {
                    *reinterpret_cast<float2*>(&C[(size_t)m * N + n]) = make_float2(lo, hi);
                }
            }
        }
    }
}

// ---- emb norms --------------------------------------------------------------
__global__ void emb_norms_kernel(const float* __restrict__ emb, float* __restrict__ enorm)
{
    int g = (blockIdx.x * blockDim.x + threadIdx.x) >> 5;
    int lane = threadIdx.x & 31;
    if (g >= NK) return;
    float a = emb[(size_t)g * 64 + lane];
    float b = emb[(size_t)g * 64 + 32 + lane];
    float s = a*a + b*b;
    #pragma unroll
    for (int off = 16; off; off >>= 1) s += __shfl_xor_sync(0xffffffffu, s, off);
    if (lane == 0) enorm[g] = s;
}

// ---------------------------------------------------------------------------
extern "C" void kernel_launch(void* const* d_in, const int* in_sizes, int n_in,
                              void* d_out, int out_size)
{
    const float* x   = (const float*)d_in[0];
    const float* W1  = (const float*)d_in[1];
    const float* b1  = (const float*)d_in[2];
    const float* W2  = (const float*)d_in[3];
    const float* b2  = (const float*)d_in[4];
    const float* W3  = (const float*)d_in[5];
    const float* b3  = (const float*)d_in[6];
    const float* W4  = (const float*)d_in[7];
    const float* b4  = (const float*)d_in[8];
    const float* emb = (const float*)d_in[9];

    float* out     = (float*)d_out;
    float* x_recon = out;
    float* z_e     = out + (size_t)NB * DIN;
    float* z_q     = z_e + (size_t)NB * DLAT;

    float *h1, *enorm; __half *h2, *H3, *a3h, *w1th, *w4t, *embh, *zeh; int *idxp, *candp;
    cudaGetSymbolAddress((void**)&h1, g_h1);
    cudaGetSymbolAddress((void**)&h2, g_h2);
    cudaGetSymbolAddress((void**)&H3, g_H3);
    cudaGetSymbolAddress((void**)&a3h, g_a3h);
    cudaGetSymbolAddress((void**)&w1th, g_w1th);
    cudaGetSymbolAddress((void**)&w4t, g_w4t);
    cudaGetSymbolAddress((void**)&embh, g_emb_h);
    cudaGetSymbolAddress((void**)&zeh, g_ze_h);
    cudaGetSymbolAddress((void**)&enorm, g_enorm);
    cudaGetSymbolAddress((void**)&idxp, g_idx);
    cudaGetSymbolAddress((void**)&candp, g_cand);

    cudaFuncSetAttribute(hmma_gemm<1>, cudaFuncAttributeMaxDynamicSharedMemorySize, MMA_SMEM);
    cudaFuncSetAttribute(hmma_gemm<2>, cudaFuncAttributeMaxDynamicSharedMemorySize, MMA_SMEM);
    cudaFuncSetAttribute(cand_kernel_h, cudaFuncAttributeMaxDynamicSharedMemorySize, CAND_SMEM_H);

    emb_norms_kernel<<<NK/8, 256>>>(emb, enorm);
    f2h_kernel<<<(NK*DLAT/4 + 255)/256, 256>>>((const float4*)emb, (__half2*)embh, NK*DLAT/4);
    {   size_t tot = (size_t)DH * KP1;
        split3_WT_h<<<(unsigned)((tot + 255)/256), 256>>>(W1, w1th, DIN, DH, DH, KP1); }
    {   size_t tot = (size_t)NPAD4 * KP4;
        round_WT_h<<<(unsigned)((tot + 255)/256), 256>>>(W4, w4t, DH, DIN, NPAD4); }

    // H3[c] = half(relu(emb[c] @ W3 + b3)) over 8192 codes
    sgemm_bias_act<128,128,16,4><<<dim3(DH/128, NK/128), 256>>>(
        emb, W3, b3, (float*)H3, NK, DH, DLAT);

    {   size_t tot = (size_t)NB * (DIN/4);
        split3_A_h<<<(unsigned)((tot + 255)/256), 256>>>(x, a3h, DIN, KP1);
        size_t tt = (size_t)NB * (KP1 - 3*DIN);
        zero_tail_A_h<<<(unsigned)((tt + 255)/256), 256>>>(a3h, 3*DIN, KP1); }

    // h1 = relu((x @ 64*W1)/64 + b1)   [3xFP16 split — argmin-safe]
    hmma_gemm<1><<<dim3(DH/128, NB/128), 256, MMA_SMEM>>>(
        a3h, w1th, b1, h1, KP1, DH, INV_WSCALE);

    // z_e = h1 @ W2 + b2  (exact fp32 FFMA)
    sgemm_bias_act<128,64,16,0><<<dim3(1, NB/128), 128>>>(h1, W2, b2, z_e, NB, DLAT, DH);

    // z_e -> fp16 for approx phase
    f2h_kernel<<<(NB*DLAT/4 + 255)/256, 256>>>((const float4*)z_e, (__half2*)zeh, NB*DLAT/4);

    // argmin: fp16 approx tensor phase + exact fp32 rescore (+ fused z_q write)
    cand_kernel_h<<<NB/128, 256, CAND_SMEM_H>>>(zeh, embh, enorm, candp);
    rescore_kernel<<<NB/4, 256>>>(z_e, emb, enorm, candp, idxp, z_q);

    // h2[m] = H3[idx[m]]  (row-copy gather)
    gather_h2_kernel<<<(unsigned)(((size_t)NB*128 + 255)/256), 256>>>(idxp, H3, h2);

    // x_recon = sigmoid(h2 @ W4 + b4)
    hmma_gemm<2><<<dim3(NPAD4/128, NB/128), 256, MMA_SMEM>>>(
        h2, w4t, b4, x_recon, KP4, DIN, 1.0f);
}